// round 4
// baseline (speedup 1.0000x reference)
#include <cuda_runtime.h>

// Problem constants
#define BATCH   8
#define SEQ     4096
#define EMB     8
#define NQ      (BATCH * SEQ)        // 32768 total queries
#define KSPLIT  4
#define KCHUNK  (SEQ / KSPLIT)       // 1024 keys per block
#define KPAIRS  (KCHUNK / 2)         // 512 key pairs
#define QPB     128                  // threads per block
#define QPT     2                    // queries per thread
#define QTILE   (QPB * QPT)          // 256 queries per block

// Scratch (no allocations allowed; __device__ globals are the sanctioned path)
__device__ float g_qkv[NQ * EMB];                 // cos(x + theta), natural layout [B,S,E]
__device__ float g_part[KSPLIT * NQ * 12];        // per-(ksplit,query): acc[8], denom, pad

typedef unsigned long long u64;

// ---- packed f32x2 helpers (sm_100+) ----
__device__ __forceinline__ u64 pack2(float lo, float hi) {
    u64 r; asm("mov.b64 %0, {%1, %2};" : "=l"(r) : "f"(lo), "f"(hi)); return r;
}
__device__ __forceinline__ void unpack2(u64 v, float& lo, float& hi) {
    asm("mov.b64 {%0, %1}, %2;" : "=f"(lo), "=f"(hi) : "l"(v));
}
__device__ __forceinline__ u64 fma2(u64 a, u64 b, u64 c) {
    u64 d; asm("fma.rn.f32x2 %0, %1, %2, %3;" : "=l"(d) : "l"(a), "l"(b), "l"(c)); return d;
}
__device__ __forceinline__ u64 mul2(u64 a, u64 b) {
    u64 d; asm("mul.rn.f32x2 %0, %1, %2;" : "=l"(d) : "l"(a), "l"(b)); return d;
}
__device__ __forceinline__ u64 add2(u64 a, u64 b) {
    u64 d; asm("add.rn.f32x2 %0, %1, %2;" : "=l"(d) : "l"(a), "l"(b)); return d;
}
__device__ __forceinline__ float ex2f(float x) {
    float r; asm("ex2.approx.f32 %0, %1;" : "=f"(r) : "f"(x)); return r;
}

// ---------------------------------------------------------------------------
// Kernel 1: qkv = cos(x + theta). Half-row (4 floats) per thread.
// ---------------------------------------------------------------------------
__global__ void k_prep(const float* __restrict__ x, const float* __restrict__ theta) {
    int i = blockIdx.x * blockDim.x + threadIdx.x;   // half-row index
    if (i >= NQ * 2) return;
    int h = (i & 1) * 4;
    float t0 = theta[h + 0], t1 = theta[h + 1], t2 = theta[h + 2], t3 = theta[h + 3];
    float4 a = ((const float4*)x)[i];
    float4 o;
    o.x = __cosf(a.x + t0); o.y = __cosf(a.y + t1);
    o.z = __cosf(a.z + t2); o.w = __cosf(a.w + t3);
    ((float4*)g_qkv)[i] = o;
}

// ---------------------------------------------------------------------------
// Kernel 2: flash-style attention, no-max single-pass softmax (|s| <= 2.83).
// exp on MUFU (dot pre-scaled by log2e), 2 keys packed in f32x2, and
// TWO queries per thread so each K smem read is amortized 2x (the smem
// crossbar was the R3 bottleneck: 512B/LDS.128 broadcast at 128B/cyc/SM).
// ---------------------------------------------------------------------------
__global__ void __launch_bounds__(QPB) k_attn() {
    // K tile packed as pairs: smk[pair p][d][slot] ; slot0 = even key, slot1 = odd
    __shared__ __align__(16) float smk[KPAIRS * 16];   // 32 KB

    const int qtile = blockIdx.x;          // 0..127  (16 tiles of 256 per batch)
    const int ks    = blockIdx.y;          // 0..KSPLIT-1
    const int b     = qtile >> 4;          // 16 query tiles per batch
    const int qA    = qtile * QTILE + threadIdx.x;   // first query
    const int qB    = qA + QPB;                      // second query

    // ---- fill smem with this block's 1024-key chunk, pair-interleaved ----
    const float* kbase = g_qkv + ((size_t)b * SEQ + (size_t)ks * KCHUNK) * EMB;
    for (int p = threadIdx.x; p < KPAIRS; p += QPB) {
        const float4* e4 = (const float4*)(kbase + (size_t)(2 * p) * 8);
        float4 e0 = e4[0], e1 = e4[1];     // even key
        float4 o0 = e4[2], o1 = e4[3];     // odd key
        float2* dst = (float2*)(smk + p * 16);
        dst[0] = make_float2(e0.x, o0.x);
        dst[1] = make_float2(e0.y, o0.y);
        dst[2] = make_float2(e0.z, o0.z);
        dst[3] = make_float2(e0.w, o0.w);
        dst[4] = make_float2(e1.x, o1.x);
        dst[5] = make_float2(e1.y, o1.y);
        dst[6] = make_float2(e1.z, o1.z);
        dst[7] = make_float2(e1.w, o1.w);
    }
    __syncthreads();

    // ---- two per-thread queries, pre-scaled by log2(e)/sqrt(8) ----
    const float SCALE = 0.51006310094284079f;  // log2(e)/sqrt(8)
    u64 qqA[8], qqB[8];
    {
        const float4* q4 = (const float4*)(g_qkv + (size_t)qA * 8);
        float4 a = q4[0], c = q4[1];
        float s[8] = {a.x, a.y, a.z, a.w, c.x, c.y, c.z, c.w};
#pragma unroll
        for (int d = 0; d < 8; ++d) { float v = s[d] * SCALE; qqA[d] = pack2(v, v); }
    }
    {
        const float4* q4 = (const float4*)(g_qkv + (size_t)qB * 8);
        float4 a = q4[0], c = q4[1];
        float s[8] = {a.x, a.y, a.z, a.w, c.x, c.y, c.z, c.w};
#pragma unroll
        for (int d = 0; d < 8; ++d) { float v = s[d] * SCALE; qqB[d] = pack2(v, v); }
    }

    u64 aA0 = 0, aA1 = 0, aA2 = 0, aA3 = 0, aA4 = 0, aA5 = 0, aA6 = 0, aA7 = 0;
    u64 aB0 = 0, aB1 = 0, aB2 = 0, aB3 = 0, aB4 = 0, aB5 = 0, aB6 = 0, aB7 = 0;
    u64 denA = 0, denB = 0;

#pragma unroll 2
    for (int p = 0; p < KPAIRS; ++p) {
        const ulonglong2* sp = (const ulonglong2*)smk + (size_t)p * 4;
        ulonglong2 v0 = sp[0], v1 = sp[1], v2 = sp[2], v3 = sp[3];
        u64 k0 = v0.x, k1 = v0.y, k2 = v1.x, k3 = v1.y;
        u64 k4 = v2.x, k5 = v2.y, k6 = v3.x, k7 = v3.y;

        // two independent packed dot chains (ILP)
        u64 uA = mul2(qqA[0], k0);
        u64 uB = mul2(qqB[0], k0);
        uA = fma2(qqA[1], k1, uA);  uB = fma2(qqB[1], k1, uB);
        uA = fma2(qqA[2], k2, uA);  uB = fma2(qqB[2], k2, uB);
        uA = fma2(qqA[3], k3, uA);  uB = fma2(qqB[3], k3, uB);
        uA = fma2(qqA[4], k4, uA);  uB = fma2(qqB[4], k4, uB);
        uA = fma2(qqA[5], k5, uA);  uB = fma2(qqB[5], k5, uB);
        uA = fma2(qqA[6], k6, uA);  uB = fma2(qqB[6], k6, uB);
        uA = fma2(qqA[7], k7, uA);  uB = fma2(qqB[7], k7, uB);

        // w = 2^u per half on the MUFU pipe
        float lA, hA, lB, hB;
        unpack2(uA, lA, hA);
        unpack2(uB, lB, hB);
        u64 wA = pack2(ex2f(lA), ex2f(hA));
        u64 wB = pack2(ex2f(lB), ex2f(hB));

        // V accumulate (v == k) + denominators
        aA0 = fma2(k0, wA, aA0);   aB0 = fma2(k0, wB, aB0);
        aA1 = fma2(k1, wA, aA1);   aB1 = fma2(k1, wB, aB1);
        aA2 = fma2(k2, wA, aA2);   aB2 = fma2(k2, wB, aB2);
        aA3 = fma2(k3, wA, aA3);   aB3 = fma2(k3, wB, aB3);
        aA4 = fma2(k4, wA, aA4);   aB4 = fma2(k4, wB, aB4);
        aA5 = fma2(k5, wA, aA5);   aB5 = fma2(k5, wB, aB5);
        aA6 = fma2(k6, wA, aA6);   aB6 = fma2(k6, wB, aB6);
        aA7 = fma2(k7, wA, aA7);   aB7 = fma2(k7, wB, aB7);
        denA = add2(denA, wA);
        denB = add2(denB, wB);
    }

    // ---- reduce packed halves, write partials ----
    float lo, hi, res[8];
    {
        u64 accs[8] = {aA0, aA1, aA2, aA3, aA4, aA5, aA6, aA7};
        float* out = g_part + ((size_t)ks * NQ + qA) * 12;
#pragma unroll
        for (int d = 0; d < 8; ++d) { unpack2(accs[d], lo, hi); res[d] = lo + hi; }
        ((float4*)out)[0] = make_float4(res[0], res[1], res[2], res[3]);
        ((float4*)out)[1] = make_float4(res[4], res[5], res[6], res[7]);
        unpack2(denA, lo, hi);
        out[8] = lo + hi;
    }
    {
        u64 accs[8] = {aB0, aB1, aB2, aB3, aB4, aB5, aB6, aB7};
        float* out = g_part + ((size_t)ks * NQ + qB) * 12;
#pragma unroll
        for (int d = 0; d < 8; ++d) { unpack2(accs[d], lo, hi); res[d] = lo + hi; }
        ((float4*)out)[0] = make_float4(res[0], res[1], res[2], res[3]);
        ((float4*)out)[1] = make_float4(res[4], res[5], res[6], res[7]);
        unpack2(denB, lo, hi);
        out[8] = lo + hi;
    }
}

// ---------------------------------------------------------------------------
// Kernel 3: combine ksplit partials, normalize, apply W_out^T
// ---------------------------------------------------------------------------
__global__ void k_fin(const float* __restrict__ W, float* __restrict__ out) {
    __shared__ float sw[64];
    if (threadIdx.x < 64) sw[threadIdx.x] = W[threadIdx.x];
    __syncthreads();

    int q = blockIdx.x * blockDim.x + threadIdx.x;
    if (q >= NQ) return;

    float acc[8] = {0, 0, 0, 0, 0, 0, 0, 0};
    float den = 0.0f;
#pragma unroll
    for (int ks = 0; ks < KSPLIT; ++ks) {
        const float* p = g_part + ((size_t)ks * NQ + q) * 12;
        float4 pa = ((const float4*)p)[0];
        float4 pb = ((const float4*)p)[1];
        acc[0] += pa.x; acc[1] += pa.y; acc[2] += pa.z; acc[3] += pa.w;
        acc[4] += pb.x; acc[5] += pb.y; acc[6] += pb.z; acc[7] += pb.w;
        den += p[8];
    }
    float inv = 1.0f / den;
    float o[8];
#pragma unroll
    for (int d = 0; d < 8; ++d) o[d] = acc[d] * inv;

    float r[8];
#pragma unroll
    for (int e = 0; e < 8; ++e) {
        float s = 0.0f;
#pragma unroll
        for (int d = 0; d < 8; ++d) s = fmaf(o[d], sw[e * 8 + d], s);
        r[e] = s;
    }
    float4* op = (float4*)(out + (size_t)q * 8);
    op[0] = make_float4(r[0], r[1], r[2], r[3]);
    op[1] = make_float4(r[4], r[5], r[6], r[7]);
}

// ---------------------------------------------------------------------------
extern "C" void kernel_launch(void* const* d_in, const int* in_sizes, int n_in,
                              void* d_out, int out_size) {
    const float* x     = (const float*)d_in[0];   // [8,4096,8] f32
    const float* theta = (const float*)d_in[1];   // [8] f32
    const float* W_out = (const float*)d_in[2];   // [8,8] f32
    float* out = (float*)d_out;                   // [8,4096,8] f32

    k_prep<<<(NQ * 2 + 255) / 256, 256>>>(x, theta);
    k_attn<<<dim3(NQ / QTILE, KSPLIT), QPB>>>();
    k_fin<<<(NQ + 255) / 256, 256>>>(W_out, out);
}

// round 5
// speedup vs baseline: 1.0012x; 1.0012x over previous
#include <cuda_runtime.h>

// Problem constants
#define BATCH   8
#define SEQ     4096
#define EMB     8
#define NQ      (BATCH * SEQ)        // 32768 total queries
#define KSPLIT  4
#define KCHUNK  (SEQ / KSPLIT)       // 1024 keys per block
#define KPAIRS  (KCHUNK / 2)         // 512 key pairs
#define QPB     128                  // threads per block
#define QPT     2                    // queries per thread
#define QTILE   (QPB * QPT)          // 256 queries per block

// Scratch (no allocations allowed; __device__ globals are the sanctioned path)
__device__ float g_qkv[NQ * EMB];                 // cos(x + theta), natural layout [B,S,E]
__device__ float g_part[KSPLIT * NQ * 12];        // per-(ksplit,query): acc[8], denom, pad

typedef unsigned long long u64;

// ---- packed f32x2 helpers (sm_100+) ----
__device__ __forceinline__ u64 pack2(float lo, float hi) {
    u64 r; asm("mov.b64 %0, {%1, %2};" : "=l"(r) : "f"(lo), "f"(hi)); return r;
}
__device__ __forceinline__ void unpack2(u64 v, float& lo, float& hi) {
    asm("mov.b64 {%0, %1}, %2;" : "=f"(lo), "=f"(hi) : "l"(v));
}
__device__ __forceinline__ u64 fma2(u64 a, u64 b, u64 c) {
    u64 d; asm("fma.rn.f32x2 %0, %1, %2, %3;" : "=l"(d) : "l"(a), "l"(b), "l"(c)); return d;
}
__device__ __forceinline__ u64 mul2(u64 a, u64 b) {
    u64 d; asm("mul.rn.f32x2 %0, %1, %2;" : "=l"(d) : "l"(a), "l"(b)); return d;
}
__device__ __forceinline__ u64 add2(u64 a, u64 b) {
    u64 d; asm("add.rn.f32x2 %0, %1, %2;" : "=l"(d) : "l"(a), "l"(b)); return d;
}
__device__ __forceinline__ float ex2f(float x) {
    float r; asm("ex2.approx.f32 %0, %1;" : "=f"(r) : "f"(x)); return r;
}

// ---------------------------------------------------------------------------
// Kernel 1: qkv = cos(x + theta). Half-row (4 floats) per thread.
// ---------------------------------------------------------------------------
__global__ void k_prep(const float* __restrict__ x, const float* __restrict__ theta) {
    int i = blockIdx.x * blockDim.x + threadIdx.x;   // half-row index
    if (i >= NQ * 2) return;
    int h = (i & 1) * 4;
    float t0 = theta[h + 0], t1 = theta[h + 1], t2 = theta[h + 2], t3 = theta[h + 3];
    float4 a = ((const float4*)x)[i];
    float4 o;
    o.x = __cosf(a.x + t0); o.y = __cosf(a.y + t1);
    o.z = __cosf(a.z + t2); o.w = __cosf(a.w + t3);
    ((float4*)g_qkv)[i] = o;
}

// ---------------------------------------------------------------------------
// Kernel 2: flash-style attention, no-max single-pass softmax (|s| <= 2.83).
// exp on MUFU (dot pre-scaled by log2e), 2 keys packed in f32x2, and
// TWO queries per thread so each K smem read is amortized 2x (the smem
// crossbar was the R3 bottleneck: 512B/LDS.128 broadcast at 128B/cyc/SM).
// ---------------------------------------------------------------------------
__global__ void __launch_bounds__(QPB) k_attn() {
    // K tile packed as pairs: smk[pair p][d][slot] ; slot0 = even key, slot1 = odd
    __shared__ __align__(16) float smk[KPAIRS * 16];   // 32 KB

    const int qtile = blockIdx.x;          // 0..127  (16 tiles of 256 per batch)
    const int ks    = blockIdx.y;          // 0..KSPLIT-1
    const int b     = qtile >> 4;          // 16 query tiles per batch
    const int qA    = qtile * QTILE + threadIdx.x;   // first query
    const int qB    = qA + QPB;                      // second query

    // ---- fill smem with this block's 1024-key chunk, pair-interleaved ----
    const float* kbase = g_qkv + ((size_t)b * SEQ + (size_t)ks * KCHUNK) * EMB;
    for (int p = threadIdx.x; p < KPAIRS; p += QPB) {
        const float4* e4 = (const float4*)(kbase + (size_t)(2 * p) * 8);
        float4 e0 = e4[0], e1 = e4[1];     // even key
        float4 o0 = e4[2], o1 = e4[3];     // odd key
        float2* dst = (float2*)(smk + p * 16);
        dst[0] = make_float2(e0.x, o0.x);
        dst[1] = make_float2(e0.y, o0.y);
        dst[2] = make_float2(e0.z, o0.z);
        dst[3] = make_float2(e0.w, o0.w);
        dst[4] = make_float2(e1.x, o1.x);
        dst[5] = make_float2(e1.y, o1.y);
        dst[6] = make_float2(e1.z, o1.z);
        dst[7] = make_float2(e1.w, o1.w);
    }
    __syncthreads();

    // ---- two per-thread queries, pre-scaled by log2(e)/sqrt(8) ----
    const float SCALE = 0.51006310094284079f;  // log2(e)/sqrt(8)
    u64 qqA[8], qqB[8];
    {
        const float4* q4 = (const float4*)(g_qkv + (size_t)qA * 8);
        float4 a = q4[0], c = q4[1];
        float s[8] = {a.x, a.y, a.z, a.w, c.x, c.y, c.z, c.w};
#pragma unroll
        for (int d = 0; d < 8; ++d) { float v = s[d] * SCALE; qqA[d] = pack2(v, v); }
    }
    {
        const float4* q4 = (const float4*)(g_qkv + (size_t)qB * 8);
        float4 a = q4[0], c = q4[1];
        float s[8] = {a.x, a.y, a.z, a.w, c.x, c.y, c.z, c.w};
#pragma unroll
        for (int d = 0; d < 8; ++d) { float v = s[d] * SCALE; qqB[d] = pack2(v, v); }
    }

    u64 aA0 = 0, aA1 = 0, aA2 = 0, aA3 = 0, aA4 = 0, aA5 = 0, aA6 = 0, aA7 = 0;
    u64 aB0 = 0, aB1 = 0, aB2 = 0, aB3 = 0, aB4 = 0, aB5 = 0, aB6 = 0, aB7 = 0;
    u64 denA = 0, denB = 0;

#pragma unroll 2
    for (int p = 0; p < KPAIRS; ++p) {
        const ulonglong2* sp = (const ulonglong2*)smk + (size_t)p * 4;
        ulonglong2 v0 = sp[0], v1 = sp[1], v2 = sp[2], v3 = sp[3];
        u64 k0 = v0.x, k1 = v0.y, k2 = v1.x, k3 = v1.y;
        u64 k4 = v2.x, k5 = v2.y, k6 = v3.x, k7 = v3.y;

        // two independent packed dot chains (ILP)
        u64 uA = mul2(qqA[0], k0);
        u64 uB = mul2(qqB[0], k0);
        uA = fma2(qqA[1], k1, uA);  uB = fma2(qqB[1], k1, uB);
        uA = fma2(qqA[2], k2, uA);  uB = fma2(qqB[2], k2, uB);
        uA = fma2(qqA[3], k3, uA);  uB = fma2(qqB[3], k3, uB);
        uA = fma2(qqA[4], k4, uA);  uB = fma2(qqB[4], k4, uB);
        uA = fma2(qqA[5], k5, uA);  uB = fma2(qqB[5], k5, uB);
        uA = fma2(qqA[6], k6, uA);  uB = fma2(qqB[6], k6, uB);
        uA = fma2(qqA[7], k7, uA);  uB = fma2(qqB[7], k7, uB);

        // w = 2^u per half on the MUFU pipe
        float lA, hA, lB, hB;
        unpack2(uA, lA, hA);
        unpack2(uB, lB, hB);
        u64 wA = pack2(ex2f(lA), ex2f(hA));
        u64 wB = pack2(ex2f(lB), ex2f(hB));

        // V accumulate (v == k) + denominators
        aA0 = fma2(k0, wA, aA0);   aB0 = fma2(k0, wB, aB0);
        aA1 = fma2(k1, wA, aA1);   aB1 = fma2(k1, wB, aB1);
        aA2 = fma2(k2, wA, aA2);   aB2 = fma2(k2, wB, aB2);
        aA3 = fma2(k3, wA, aA3);   aB3 = fma2(k3, wB, aB3);
        aA4 = fma2(k4, wA, aA4);   aB4 = fma2(k4, wB, aB4);
        aA5 = fma2(k5, wA, aA5);   aB5 = fma2(k5, wB, aB5);
        aA6 = fma2(k6, wA, aA6);   aB6 = fma2(k6, wB, aB6);
        aA7 = fma2(k7, wA, aA7);   aB7 = fma2(k7, wB, aB7);
        denA = add2(denA, wA);
        denB = add2(denB, wB);
    }

    // ---- reduce packed halves, write partials ----
    float lo, hi, res[8];
    {
        u64 accs[8] = {aA0, aA1, aA2, aA3, aA4, aA5, aA6, aA7};
        float* out = g_part + ((size_t)ks * NQ + qA) * 12;
#pragma unroll
        for (int d = 0; d < 8; ++d) { unpack2(accs[d], lo, hi); res[d] = lo + hi; }
        ((float4*)out)[0] = make_float4(res[0], res[1], res[2], res[3]);
        ((float4*)out)[1] = make_float4(res[4], res[5], res[6], res[7]);
        unpack2(denA, lo, hi);
        out[8] = lo + hi;
    }
    {
        u64 accs[8] = {aB0, aB1, aB2, aB3, aB4, aB5, aB6, aB7};
        float* out = g_part + ((size_t)ks * NQ + qB) * 12;
#pragma unroll
        for (int d = 0; d < 8; ++d) { unpack2(accs[d], lo, hi); res[d] = lo + hi; }
        ((float4*)out)[0] = make_float4(res[0], res[1], res[2], res[3]);
        ((float4*)out)[1] = make_float4(res[4], res[5], res[6], res[7]);
        unpack2(denB, lo, hi);
        out[8] = lo + hi;
    }
}

// ---------------------------------------------------------------------------
// Kernel 3: combine ksplit partials, normalize, apply W_out^T
// ---------------------------------------------------------------------------
__global__ void k_fin(const float* __restrict__ W, float* __restrict__ out) {
    __shared__ float sw[64];
    if (threadIdx.x < 64) sw[threadIdx.x] = W[threadIdx.x];
    __syncthreads();

    int q = blockIdx.x * blockDim.x + threadIdx.x;
    if (q >= NQ) return;

    float acc[8] = {0, 0, 0, 0, 0, 0, 0, 0};
    float den = 0.0f;
#pragma unroll
    for (int ks = 0; ks < KSPLIT; ++ks) {
        const float* p = g_part + ((size_t)ks * NQ + q) * 12;
        float4 pa = ((const float4*)p)[0];
        float4 pb = ((const float4*)p)[1];
        acc[0] += pa.x; acc[1] += pa.y; acc[2] += pa.z; acc[3] += pa.w;
        acc[4] += pb.x; acc[5] += pb.y; acc[6] += pb.z; acc[7] += pb.w;
        den += p[8];
    }
    float inv = 1.0f / den;
    float o[8];
#pragma unroll
    for (int d = 0; d < 8; ++d) o[d] = acc[d] * inv;

    float r[8];
#pragma unroll
    for (int e = 0; e < 8; ++e) {
        float s = 0.0f;
#pragma unroll
        for (int d = 0; d < 8; ++d) s = fmaf(o[d], sw[e * 8 + d], s);
        r[e] = s;
    }
    float4* op = (float4*)(out + (size_t)q * 8);
    op[0] = make_float4(r[0], r[1], r[2], r[3]);
    op[1] = make_float4(r[4], r[5], r[6], r[7]);
}

// ---------------------------------------------------------------------------
extern "C" void kernel_launch(void* const* d_in, const int* in_sizes, int n_in,
                              void* d_out, int out_size) {
    const float* x     = (const float*)d_in[0];   // [8,4096,8] f32
    const float* theta = (const float*)d_in[1];   // [8] f32
    const float* W_out = (const float*)d_in[2];   // [8,8] f32
    float* out = (float*)d_out;                   // [8,4096,8] f32

    k_prep<<<(NQ * 2 + 255) / 256, 256>>>(x, theta);
    k_attn<<<dim3(NQ / QTILE, KSPLIT), QPB>>>();
    k_fin<<<(NQ + 255) / 256, 256>>>(W_out, out);
}

// round 6
// speedup vs baseline: 2.4943x; 2.4914x over previous
#include <cuda_runtime.h>
#include <cuda_bf16.h>
#include <cstdint>

#define BATCH   8
#define SEQ     4096
#define NQ      (BATCH * SEQ)       // 32768
#define KSPLIT  8
#define KCHUNK  (SEQ / KSPLIT)      // 512 keys per CTA
#define NSTEP   (KCHUNK / 16)       // 32 steps of 16 keys
#define QPB     128
#define KST     520                 // smem K row stride (floats):  +8 pad -> conflict-free
#define VST     520                 // smem V row stride (bf16):    +8 pad -> ldmatrix conflict-free

// __device__ scratch (no allocs allowed)
__device__ float          g_qT [8 * NQ];   // tf32-rounded cos, [dim][key]
__device__ __nv_bfloat16  g_qTb[8 * NQ];   // bf16 cos,         [dim][key]
__device__ float          g_part[KSPLIT * NQ * 12];

__device__ __forceinline__ uint32_t tf32r(float x) {
    uint32_t r; asm("cvt.rna.tf32.f32 %0, %1;" : "=r"(r) : "f"(x)); return r;
}
__device__ __forceinline__ float ex2f(float x) {
    float r; asm("ex2.approx.f32 %0, %1;" : "=f"(r) : "f"(x)); return r;
}
__device__ __forceinline__ uint32_t bf16x2(float hi, float lo) {
    uint32_t r; asm("cvt.rn.bf16x2.f32 %0, %1, %2;" : "=r"(r) : "f"(hi), "f"(lo)); return r;
}
__device__ __forceinline__ uint32_t smem_u32(const void* p) {
    uint32_t a;
    asm("{ .reg .u64 t; cvta.to.shared.u64 t, %1; cvt.u32.u64 %0, t; }" : "=r"(a) : "l"(p));
    return a;
}

// S = A(tf32) . B(tf32), C = 0
__device__ __forceinline__ void mma_tf32(float s[4],
        uint32_t a0, uint32_t a1, uint32_t a2, uint32_t a3,
        uint32_t b0, uint32_t b1) {
    asm("mma.sync.aligned.m16n8k8.row.col.f32.tf32.tf32.f32 "
        "{%0,%1,%2,%3},{%4,%5,%6,%7},{%8,%9},{%10,%11,%12,%13};"
        : "=f"(s[0]), "=f"(s[1]), "=f"(s[2]), "=f"(s[3])
        : "r"(a0), "r"(a1), "r"(a2), "r"(a3), "r"(b0), "r"(b1),
          "f"(0.0f), "f"(0.0f), "f"(0.0f), "f"(0.0f));
}

// O += A(bf16x2) . B(bf16x2)
__device__ __forceinline__ void mma_bf16(float o[4],
        uint32_t a0, uint32_t a1, uint32_t a2, uint32_t a3,
        uint32_t b0, uint32_t b1) {
    asm("mma.sync.aligned.m16n8k16.row.col.f32.bf16.bf16.f32 "
        "{%0,%1,%2,%3},{%4,%5,%6,%7},{%8,%9},{%0,%1,%2,%3};"
        : "+f"(o[0]), "+f"(o[1]), "+f"(o[2]), "+f"(o[3])
        : "r"(a0), "r"(a1), "r"(a2), "r"(a3), "r"(b0), "r"(b1));
}

__device__ __forceinline__ void ldmx2(uint32_t& r0, uint32_t& r1, uint32_t addr) {
    asm("ldmatrix.sync.aligned.m8n8.x2.shared.b16 {%0,%1}, [%2];"
        : "=r"(r0), "=r"(r1) : "r"(addr));
}

// ---------------------------------------------------------------------------
// Kernel 1: cos(x+theta) -> g_qT (tf32-rounded, [dim][key]) and g_qTb (bf16).
// Each thread handles 4 consecutive keys (all 8 dims) -> coalesced T-stores.
// ---------------------------------------------------------------------------
__global__ void k_prep(const float* __restrict__ x, const float* __restrict__ theta) {
    int i = blockIdx.x * blockDim.x + threadIdx.x;
    if (i >= NQ / 4) return;
    int key0 = i * 4;
    float th[8];
#pragma unroll
    for (int d = 0; d < 8; ++d) th[d] = theta[d];
    float v[4][8];
#pragma unroll
    for (int r = 0; r < 4; ++r) {
        const float4* xp = (const float4*)(x + (size_t)(key0 + r) * 8);
        float4 a = xp[0], b = xp[1];
        float xv[8] = {a.x, a.y, a.z, a.w, b.x, b.y, b.z, b.w};
#pragma unroll
        for (int d = 0; d < 8; ++d) v[r][d] = __cosf(xv[d] + th[d]);
    }
#pragma unroll
    for (int d = 0; d < 8; ++d) {
        float4 o;
        o.x = __uint_as_float(tf32r(v[0][d]));
        o.y = __uint_as_float(tf32r(v[1][d]));
        o.z = __uint_as_float(tf32r(v[2][d]));
        o.w = __uint_as_float(tf32r(v[3][d]));
        *(float4*)(g_qT + (size_t)d * NQ + key0) = o;
        uint2 bo;
        bo.x = bf16x2(v[1][d], v[0][d]);
        bo.y = bf16x2(v[3][d], v[2][d]);
        *(uint2*)(g_qTb + (size_t)d * NQ + key0) = bo;
    }
}

// ---------------------------------------------------------------------------
// Kernel 2: attention via mma.sync.
//  MMA1 (tf32 m16n8k8):  S[16q x 8k] = Qscaled . K^T    (2 n-tiles, 2 m-tiles)
//  exp:  EX2 on S frags (MUFU) ; den accumulated in f32
//  MMA2 (bf16 m16n8k16): O += P . V  (FA2 C->A fragment reuse, V via ldmatrix)
// ---------------------------------------------------------------------------
__global__ void __launch_bounds__(QPB) k_attn() {
    __shared__ __align__(16) float         sKt[8 * KST];   // [dim][key] tf32
    __shared__ __align__(16) __nv_bfloat16 sVb[8 * VST];   // [dim][key] bf16

    const int tid  = threadIdx.x;
    const int lane = tid & 31;
    const int warp = tid >> 5;
    const int g    = lane >> 2;      // 0..7
    const int tid4 = lane & 3;       // 0..3

    const int qt     = blockIdx.x;              // 0..255
    const int ks     = blockIdx.y;              // 0..7
    const int b      = qt >> 5;                 // 32 q-tiles per batch
    const int qrow0  = qt * 128 + warp * 32;    // first q row of this warp
    const int chunk0 = b * SEQ + ks * KCHUNK;   // first global key of this CTA

    // ---- fill smem tiles (K tf32, V bf16), [dim][key] with padded stride ----
    for (int idx = tid; idx < 8 * (KCHUNK / 4); idx += QPB) {
        int d = idx >> 7, c = idx & 127;        // KCHUNK/4 = 128 float4 per dim
        ((float4*)(sKt + d * KST))[c] = ((const float4*)(g_qT + (size_t)d * NQ + chunk0))[c];
    }
    for (int idx = tid; idx < 8 * (KCHUNK / 8); idx += QPB) {
        int d = idx >> 6, c = idx & 63;         // KCHUNK/8 = 64 uint4 per dim
        ((uint4*)(sVb + d * VST))[c] = ((const uint4*)(g_qTb + (size_t)d * NQ + chunk0))[c];
    }

    // ---- Q A-fragments (2 m-tiles), scaled by log2(e)/sqrt(8), tf32 ----
    const float SCALE = 0.51006310094284079f;
    uint32_t qa0[2], qa1[2], qa2[2], qa3[2];
#pragma unroll
    for (int mt = 0; mt < 2; ++mt) {
        int r0 = qrow0 + mt * 16 + g;
        qa0[mt] = tf32r(g_qT[(size_t)tid4 * NQ + r0] * SCALE);
        qa1[mt] = tf32r(g_qT[(size_t)tid4 * NQ + r0 + 8] * SCALE);
        qa2[mt] = tf32r(g_qT[(size_t)(tid4 + 4) * NQ + r0] * SCALE);
        qa3[mt] = tf32r(g_qT[(size_t)(tid4 + 4) * NQ + r0 + 8] * SCALE);
    }
    __syncthreads();

    float o[2][4] = {{0, 0, 0, 0}, {0, 0, 0, 0}};
    float den[2][2] = {{0, 0}, {0, 0}};

    // ldmatrix V row base: threads 0-7 -> matrix0 rows (keys k0..k0+7),
    // threads 8-15 -> matrix1 rows (keys k0+8..k0+15); rows are dims.
    const int vrow = lane & 7;
    const int voff = ((lane & 15) >= 8) ? 8 : 0;
    const uint32_t vbase = smem_u32(sVb + vrow * VST + voff);

#pragma unroll 2
    for (int s = 0; s < NSTEP; ++s) {
        const int k0 = s * 16;
        // B1 (K^T) tf32: b0: k=dim tid4, n=key g ; b1: dim tid4+4
        uint32_t b0a = __float_as_uint(sKt[tid4 * KST + k0 + g]);
        uint32_t b1a = __float_as_uint(sKt[(tid4 + 4) * KST + k0 + g]);
        uint32_t b0b = __float_as_uint(sKt[tid4 * KST + k0 + 8 + g]);
        uint32_t b1b = __float_as_uint(sKt[(tid4 + 4) * KST + k0 + 8 + g]);
        // V b-frags (bf16): keys = reduction dim, dims = n
        uint32_t vb0, vb1;
        ldmx2(vb0, vb1, vbase + (uint32_t)k0 * 2);

#pragma unroll
        for (int mt = 0; mt < 2; ++mt) {
            float s1[4], s2[4];
            mma_tf32(s1, qa0[mt], qa1[mt], qa2[mt], qa3[mt], b0a, b1a);
            mma_tf32(s2, qa0[mt], qa1[mt], qa2[mt], qa3[mt], b0b, b1b);
#pragma unroll
            for (int i = 0; i < 4; ++i) { s1[i] = ex2f(s1[i]); s2[i] = ex2f(s2[i]); }
            den[mt][0] += s1[0] + s1[1] + s2[0] + s2[1];
            den[mt][1] += s1[2] + s1[3] + s2[2] + s2[3];
            // P -> bf16 A-frags: a0/a1 keys 0-7 (rows g, g+8), a2/a3 keys 8-15
            uint32_t pa0 = bf16x2(s1[1], s1[0]);
            uint32_t pa1 = bf16x2(s1[3], s1[2]);
            uint32_t pa2 = bf16x2(s2[1], s2[0]);
            uint32_t pa3 = bf16x2(s2[3], s2[2]);
            mma_bf16(o[mt], pa0, pa1, pa2, pa3, vb0, vb1);
        }
    }

    // ---- reduce den across the 4 col-threads (lanes g*4 + 0..3) ----
#pragma unroll
    for (int mt = 0; mt < 2; ++mt) {
#pragma unroll
        for (int r = 0; r < 2; ++r) {
            den[mt][r] += __shfl_xor_sync(0xFFFFFFFF, den[mt][r], 1);
            den[mt][r] += __shfl_xor_sync(0xFFFFFFFF, den[mt][r], 2);
        }
    }

    // ---- write partials: O frag row g -> dims 2*tid4, 2*tid4+1 ----
#pragma unroll
    for (int mt = 0; mt < 2; ++mt) {
        int q0 = qrow0 + mt * 16 + g;
        float* p = g_part + ((size_t)ks * NQ + q0) * 12;
        *(float2*)(p + 2 * tid4) = make_float2(o[mt][0], o[mt][1]);
        if (tid4 == 0) p[8] = den[mt][0];
        float* p2 = g_part + ((size_t)ks * NQ + q0 + 8) * 12;
        *(float2*)(p2 + 2 * tid4) = make_float2(o[mt][2], o[mt][3]);
        if (tid4 == 0) p2[8] = den[mt][1];
    }
}

// ---------------------------------------------------------------------------
// Kernel 3: combine ksplit partials, normalize, apply W_out^T
// ---------------------------------------------------------------------------
__global__ void k_fin(const float* __restrict__ W, float* __restrict__ out) {
    __shared__ float sw[64];
    if (threadIdx.x < 64) sw[threadIdx.x] = W[threadIdx.x];
    __syncthreads();

    int q = blockIdx.x * blockDim.x + threadIdx.x;
    if (q >= NQ) return;

    float acc[8] = {0, 0, 0, 0, 0, 0, 0, 0};
    float den = 0.0f;
#pragma unroll
    for (int ks = 0; ks < KSPLIT; ++ks) {
        const float* p = g_part + ((size_t)ks * NQ + q) * 12;
        float4 pa = ((const float4*)p)[0];
        float4 pb = ((const float4*)p)[1];
        acc[0] += pa.x; acc[1] += pa.y; acc[2] += pa.z; acc[3] += pa.w;
        acc[4] += pb.x; acc[5] += pb.y; acc[6] += pb.z; acc[7] += pb.w;
        den += p[8];
    }
    float inv = 1.0f / den;
    float ov[8];
#pragma unroll
    for (int d = 0; d < 8; ++d) ov[d] = acc[d] * inv;

    float r[8];
#pragma unroll
    for (int e = 0; e < 8; ++e) {
        float s = 0.0f;
#pragma unroll
        for (int d = 0; d < 8; ++d) s = fmaf(ov[d], sw[e * 8 + d], s);
        r[e] = s;
    }
    float4* op = (float4*)(out + (size_t)q * 8);
    op[0] = make_float4(r[0], r[1], r[2], r[3]);
    op[1] = make_float4(r[4], r[5], r[6], r[7]);
}

// ---------------------------------------------------------------------------
extern "C" void kernel_launch(void* const* d_in, const int* in_sizes, int n_in,
                              void* d_out, int out_size) {
    const float* x     = (const float*)d_in[0];   // [8,4096,8] f32
    const float* theta = (const float*)d_in[1];   // [8] f32
    const float* W_out = (const float*)d_in[2];   // [8,8] f32
    float* out = (float*)d_out;                   // [8,4096,8] f32

    k_prep<<<(NQ / 4 + 255) / 256, 256>>>(x, theta);
    k_attn<<<dim3(NQ / 128, KSPLIT), QPB>>>();
    k_fin<<<(NQ + 255) / 256, 256>>>(W_out, out);
}

// round 7
// speedup vs baseline: 2.7251x; 1.0925x over previous
#include <cuda_runtime.h>
#include <cuda_bf16.h>
#include <cstdint>

#define BATCH   8
#define SEQ     4096
#define NQ      (BATCH * SEQ)       // 32768
#define NTILE   32                  // 128-row tiles per batch
#define NPAIR   528                 // NTILE*(NTILE+1)/2
#define QPB     128
#define KST     136                 // sKt row stride (floats)
#define VST     136                 // sV row stride (bf16)
#define WST     136                 // sW row stride (bf16)
#define PSTRIDE 10                  // floats per partial record

// __device__ scratch (no allocs allowed)
__device__ float          g_qT [8 * NQ];   // tf32-rounded cos, [dim][key]
__device__ __nv_bfloat16  g_qTb[8 * NQ];   // bf16 cos,         [dim][key]
__device__ float          g_part[NTILE * NQ * PSTRIDE];   // 42 MB partials

#define ONESB 0x3F803F80u   // bf16x2 (1.0, 1.0)

__device__ __forceinline__ uint32_t tf32r(float x) {
    uint32_t r; asm("cvt.rna.tf32.f32 %0, %1;" : "=r"(r) : "f"(x)); return r;
}
__device__ __forceinline__ float ex2f(float x) {
    float r; asm("ex2.approx.f32 %0, %1;" : "=f"(r) : "f"(x)); return r;
}
__device__ __forceinline__ uint32_t bf16x2(float hi, float lo) {
    uint32_t r; asm("cvt.rn.bf16x2.f32 %0, %1, %2;" : "=r"(r) : "f"(hi), "f"(lo)); return r;
}
__device__ __forceinline__ uint32_t smem_u32(const void* p) {
    uint32_t a;
    asm("{ .reg .u64 t; cvta.to.shared.u64 t, %1; cvt.u32.u64 %0, t; }" : "=r"(a) : "l"(p));
    return a;
}

__device__ __forceinline__ void mma_tf32(float s[4],
        uint32_t a0, uint32_t a1, uint32_t a2, uint32_t a3,
        uint32_t b0, uint32_t b1) {
    asm("mma.sync.aligned.m16n8k8.row.col.f32.tf32.tf32.f32 "
        "{%0,%1,%2,%3},{%4,%5,%6,%7},{%8,%9},{%10,%11,%12,%13};"
        : "=f"(s[0]), "=f"(s[1]), "=f"(s[2]), "=f"(s[3])
        : "r"(a0), "r"(a1), "r"(a2), "r"(a3), "r"(b0), "r"(b1),
          "f"(0.0f), "f"(0.0f), "f"(0.0f), "f"(0.0f));
}
__device__ __forceinline__ void mma_bf16(float o[4],
        uint32_t a0, uint32_t a1, uint32_t a2, uint32_t a3,
        uint32_t b0, uint32_t b1) {
    asm("mma.sync.aligned.m16n8k16.row.col.f32.bf16.bf16.f32 "
        "{%0,%1,%2,%3},{%4,%5,%6,%7},{%8,%9},{%0,%1,%2,%3};"
        : "+f"(o[0]), "+f"(o[1]), "+f"(o[2]), "+f"(o[3])
        : "r"(a0), "r"(a1), "r"(a2), "r"(a3), "r"(b0), "r"(b1));
}
__device__ __forceinline__ void ldmx2(uint32_t& r0, uint32_t& r1, uint32_t addr) {
    asm("ldmatrix.sync.aligned.m8n8.x2.shared.b16 {%0,%1}, [%2];"
        : "=r"(r0), "=r"(r1) : "r"(addr));
}
__device__ __forceinline__ void ldmx4t(uint32_t& r0, uint32_t& r1, uint32_t& r2, uint32_t& r3,
                                       uint32_t addr) {
    asm("ldmatrix.sync.aligned.m8n8.x4.trans.shared.b16 {%0,%1,%2,%3}, [%4];"
        : "=r"(r0), "=r"(r1), "=r"(r2), "=r"(r3) : "r"(addr));
}

// ---------------------------------------------------------------------------
// Kernel 1: cos(x+theta) -> g_qT (tf32, [dim][key]) and g_qTb (bf16). 1 key/thread.
// ---------------------------------------------------------------------------
__global__ void k_prep(const float* __restrict__ x, const float* __restrict__ theta) {
    int key = blockIdx.x * blockDim.x + threadIdx.x;
    if (key >= NQ) return;
    float th[8];
#pragma unroll
    for (int d = 0; d < 8; ++d) th[d] = theta[d];
    const float4* xp = (const float4*)(x + (size_t)key * 8);
    float4 a = xp[0], b = xp[1];
    float xv[8] = {a.x, a.y, a.z, a.w, b.x, b.y, b.z, b.w};
#pragma unroll
    for (int d = 0; d < 8; ++d) {
        float v = __cosf(xv[d] + th[d]);
        g_qT [d * NQ + key] = __uint_as_float(tf32r(v));
        g_qTb[d * NQ + key] = __float2bfloat16(v);
    }
}

// ---------------------------------------------------------------------------
// Kernel 2: symmetric-pair attention. CTA = (batch b, tile pair i<=j).
//  Phase 1: W = exp(scale*Qi.Kj^T) [tf32 mma -> EX2], direct O_i/den_i via
//           bf16 mma (den via ones-B mma), W stored bf16 to smem.
//  Phase 2 (i!=j): Wt fragments via ldmatrix.x4.trans, O_j/den_j vs V_i.
// ---------------------------------------------------------------------------
__global__ void __launch_bounds__(QPB) k_attn() {
    __shared__ __align__(16) float         sKt[8 * KST];     // K tile j tf32 [dim][key]
    __shared__ __align__(16) __nv_bfloat16 sVj[8 * VST];     // V tile j bf16 [dim][key]
    __shared__ __align__(16) __nv_bfloat16 sVi[8 * VST];     // V tile i bf16 [dim][key]
    __shared__ __align__(16) __nv_bfloat16 sW [128 * WST];   // P tile bf16 [qi][kj]

    const int tid  = threadIdx.x;
    const int lane = tid & 31;
    const int warp = tid >> 5;
    const int g    = lane >> 2;
    const int tid4 = lane & 3;

    // ---- decode (b, i, j) from triangular pair index ----
    const int b = blockIdx.y;
    const int p = blockIdx.x;
    int i = (int)((65.0f - sqrtf(4225.0f - 8.0f * (float)p)) * 0.5f);
    if (i > 31) i = 31;
    while (i > 0 && (i * (65 - i)) / 2 > p) --i;
    while (((i + 1) * (64 - i)) / 2 <= p) ++i;
    const int j = i + (p - (i * (65 - i)) / 2);

    const int ki0 = b * SEQ + i * 128;   // tile i key/query base (global)
    const int kj0 = b * SEQ + j * 128;   // tile j key/query base

    // ---- fill smem tiles ----
    for (int idx = tid; idx < 256; idx += QPB) {      // sKt: 8 dims x 32 float4
        int d = idx >> 5, c = idx & 31;
        ((float4*)(sKt + d * KST))[c] = ((const float4*)(g_qT + d * NQ + kj0))[c];
    }
    for (int idx = tid; idx < 256; idx += QPB) {      // sVj + sVi: 8 dims x 16 uint4 each
        int d = (idx >> 4) & 7, c = idx & 15;
        if (idx < 128)
            ((uint4*)(sVj + d * VST))[c] = ((const uint4*)(g_qTb + d * NQ + kj0))[c];
        else
            ((uint4*)(sVi + d * VST))[c] = ((const uint4*)(g_qTb + d * NQ + ki0))[c];
    }

    // ---- Q fragments (tile i rows), scaled by log2(e)/sqrt(8), tf32 ----
    const float SCALE = 0.51006310094284079f;
    uint32_t qa0[2], qa1[2], qa2[2], qa3[2];
#pragma unroll
    for (int mt = 0; mt < 2; ++mt) {
        int r0 = ki0 + warp * 32 + mt * 16 + g;
        qa0[mt] = tf32r(g_qT[tid4 * NQ + r0] * SCALE);
        qa1[mt] = tf32r(g_qT[tid4 * NQ + r0 + 8] * SCALE);
        qa2[mt] = tf32r(g_qT[(tid4 + 4) * NQ + r0] * SCALE);
        qa3[mt] = tf32r(g_qT[(tid4 + 4) * NQ + r0 + 8] * SCALE);
    }
    __syncthreads();

    const int vrow = lane & 7;
    const int voff = ((lane & 15) >= 8) ? 8 : 0;
    const uint32_t vbj = smem_u32(sVj + vrow * VST + voff);
    const uint32_t vbi = smem_u32(sVi + vrow * VST + voff);
    uint32_t* sW32 = (uint32_t*)sW;

    float o[2][4]  = {{0, 0, 0, 0}, {0, 0, 0, 0}};
    float dn[2][4] = {{0, 0, 0, 0}, {0, 0, 0, 0}};

    // ======== Phase 1: direct direction ========
#pragma unroll 2
    for (int s = 0; s < 8; ++s) {
        const int k0 = s * 16;
        uint32_t b0a = __float_as_uint(sKt[tid4 * KST + k0 + g]);
        uint32_t b1a = __float_as_uint(sKt[(tid4 + 4) * KST + k0 + g]);
        uint32_t b0b = __float_as_uint(sKt[tid4 * KST + k0 + 8 + g]);
        uint32_t b1b = __float_as_uint(sKt[(tid4 + 4) * KST + k0 + 8 + g]);
        uint32_t vb0, vb1;
        ldmx2(vb0, vb1, vbj + (uint32_t)k0 * 2);

#pragma unroll
        for (int mt = 0; mt < 2; ++mt) {
            float s1[4], s2[4];
            mma_tf32(s1, qa0[mt], qa1[mt], qa2[mt], qa3[mt], b0a, b1a);
            mma_tf32(s2, qa0[mt], qa1[mt], qa2[mt], qa3[mt], b0b, b1b);
#pragma unroll
            for (int t = 0; t < 4; ++t) { s1[t] = ex2f(s1[t]); s2[t] = ex2f(s2[t]); }
            uint32_t pa0 = bf16x2(s1[1], s1[0]);
            uint32_t pa1 = bf16x2(s1[3], s1[2]);
            uint32_t pa2 = bf16x2(s2[1], s2[0]);
            uint32_t pa3 = bf16x2(s2[3], s2[2]);
            // store P tile (bf16x2 words) for phase 2
            int row0 = warp * 32 + mt * 16 + g;
            sW32[row0 * (WST / 2) + (k0 >> 1) + tid4]           = pa0;
            sW32[(row0 + 8) * (WST / 2) + (k0 >> 1) + tid4]     = pa1;
            sW32[row0 * (WST / 2) + ((k0 + 8) >> 1) + tid4]     = pa2;
            sW32[(row0 + 8) * (WST / 2) + ((k0 + 8) >> 1) + tid4] = pa3;
            // direct O and den
            mma_bf16(o[mt],  pa0, pa1, pa2, pa3, vb0, vb1);
            mma_bf16(dn[mt], pa0, pa1, pa2, pa3, ONESB, ONESB);
        }
    }
    __syncthreads();   // sW complete before phase-2 reads

    // ---- phase-1 partial writes: queries tile i, slot j ----
#pragma unroll
    for (int mt = 0; mt < 2; ++mt) {
        int q0 = ki0 + warp * 32 + mt * 16 + g;
        float* pp = g_part + ((size_t)j * NQ + q0) * PSTRIDE;
        *(float2*)(pp + 2 * tid4) = make_float2(o[mt][0], o[mt][1]);
        if (tid4 == 0) pp[8] = dn[mt][0];
        float* pq = g_part + ((size_t)j * NQ + q0 + 8) * PSTRIDE;
        *(float2*)(pq + 2 * tid4) = make_float2(o[mt][2], o[mt][3]);
        if (tid4 == 0) pq[8] = dn[mt][2];
    }

    // ======== Phase 2: transposed direction (off-diagonal only) ========
    if (i != j) {
        float o2[2][4]  = {{0, 0, 0, 0}, {0, 0, 0, 0}};
        float dn2[2][4] = {{0, 0, 0, 0}, {0, 0, 0, 0}};

        const int lr  = lane & 7;
        const int sel = lane >> 3;
        const int rowb = lr + ((sel & 2) ? 8 : 0);            // W-row offset
        const int colb = warp * 32 + ((sel & 1) ? 8 : 0);     // W-col base (this warp)
        const uint32_t sWu = smem_u32(sW);

#pragma unroll 2
        for (int s = 0; s < 8; ++s) {
            const int c0 = s * 16;                            // reduction = tile-i rows
            uint32_t vb0, vb1;
            ldmx2(vb0, vb1, vbi + (uint32_t)c0 * 2);
#pragma unroll
            for (int mt = 0; mt < 2; ++mt) {
                uint32_t a0, a1, a2, a3;
                ldmx4t(a0, a1, a2, a3,
                       sWu + (uint32_t)(((c0 + rowb) * WST + colb + mt * 16) * 2));
                mma_bf16(o2[mt],  a0, a1, a2, a3, vb0, vb1);
                mma_bf16(dn2[mt], a0, a1, a2, a3, ONESB, ONESB);
            }
        }

        // writes: queries tile j, slot i
#pragma unroll
        for (int mt = 0; mt < 2; ++mt) {
            int q0 = kj0 + warp * 32 + mt * 16 + g;
            float* pp = g_part + ((size_t)i * NQ + q0) * PSTRIDE;
            *(float2*)(pp + 2 * tid4) = make_float2(o2[mt][0], o2[mt][1]);
            if (tid4 == 0) pp[8] = dn2[mt][0];
            float* pq = g_part + ((size_t)i * NQ + q0 + 8) * PSTRIDE;
            *(float2*)(pq + 2 * tid4) = make_float2(o2[mt][2], o2[mt][3]);
            if (tid4 == 0) pq[8] = dn2[mt][2];
        }
    }
}

// ---------------------------------------------------------------------------
// Kernel 3: combine 32 partials/query, normalize, apply W_out^T.
// 4 threads per query (8 slots each) + quad shuffle reduce.
// ---------------------------------------------------------------------------
__global__ void k_fin(const float* __restrict__ W, float* __restrict__ out) {
    __shared__ float sw[64];
    if (threadIdx.x < 64) sw[threadIdx.x] = W[threadIdx.x];
    __syncthreads();

    int idx = blockIdx.x * blockDim.x + threadIdx.x;   // NQ*4 threads
    int q = idx >> 2, sub = idx & 3;
    if (q >= NQ) return;

    float acc[8] = {0, 0, 0, 0, 0, 0, 0, 0};
    float den = 0.0f;
#pragma unroll
    for (int s = 0; s < 8; ++s) {
        const float* pp = g_part + ((size_t)(sub * 8 + s) * NQ + q) * PSTRIDE;
        float2 a0 = ((const float2*)pp)[0];
        float2 a1 = ((const float2*)pp)[1];
        float2 a2 = ((const float2*)pp)[2];
        float2 a3 = ((const float2*)pp)[3];
        acc[0] += a0.x; acc[1] += a0.y; acc[2] += a1.x; acc[3] += a1.y;
        acc[4] += a2.x; acc[5] += a2.y; acc[6] += a3.x; acc[7] += a3.y;
        den += pp[8];
    }
#pragma unroll
    for (int m = 1; m <= 2; m <<= 1) {
#pragma unroll
        for (int d = 0; d < 8; ++d) acc[d] += __shfl_xor_sync(0xFFFFFFFF, acc[d], m);
        den += __shfl_xor_sync(0xFFFFFFFF, den, m);
    }
    if (sub != 0) return;

    float inv = 1.0f / den;
    float ov[8];
#pragma unroll
    for (int d = 0; d < 8; ++d) ov[d] = acc[d] * inv;
    float r[8];
#pragma unroll
    for (int e = 0; e < 8; ++e) {
        float s = 0.0f;
#pragma unroll
        for (int d = 0; d < 8; ++d) s = fmaf(ov[d], sw[e * 8 + d], s);
        r[e] = s;
    }
    float4* op = (float4*)(out + (size_t)q * 8);
    op[0] = make_float4(r[0], r[1], r[2], r[3]);
    op[1] = make_float4(r[4], r[5], r[6], r[7]);
}

// ---------------------------------------------------------------------------
extern "C" void kernel_launch(void* const* d_in, const int* in_sizes, int n_in,
                              void* d_out, int out_size) {
    const float* x     = (const float*)d_in[0];   // [8,4096,8] f32
    const float* theta = (const float*)d_in[1];   // [8] f32
    const float* W_out = (const float*)d_in[2];   // [8,8] f32
    float* out = (float*)d_out;                   // [8,4096,8] f32

    k_prep<<<(NQ + 255) / 256, 256>>>(x, theta);
    k_attn<<<dim3(NPAIR, BATCH), QPB>>>();
    k_fin<<<(NQ * 4 + 255) / 256, 256>>>(W_out, out);
}